// round 16
// baseline (speedup 1.0000x reference)
#include <cuda_runtime.h>
#include <cuda_fp16.h>
#include <math.h>
#include <stdint.h>

typedef unsigned int uint32;

#define NPTS 524288
#define TSZ  (1u << 19)
#define P1   2654435761u
#define P2   805459861u

#define KP0  128                       // layer-0 K padding (71 real cols)

// ---------------- scratch (device globals; allocation-free rule) ----------------
// Padding regions (cols 71..127 of F, rows k>=71 of W0) are BSS-zero (fp16 +0.0)
// and never written by any kernel, so they stay zero across graph replays.
__device__ __half g_F [(size_t)NPTS * KP0];
__device__ __half g_H0[(size_t)NPTS * 256];
__device__ __half g_H1[(size_t)NPTS * 256];
__device__ __half g_W0[256 * KP0];             // [N=256][Kpad] K-major
__device__ __half g_W1[256 * 256];
__device__ __half g_W2[256 * 256];             // rows 0..255 of v2
__device__ float  g_w2last[256];               // row 256 of v2 (folded)

struct LevelParams { int R[16]; int dense[16]; };

// ---------------- PTX helpers ---------------------------------------------------
__device__ __forceinline__ uint32 smem_u32(const void* p) {
    uint32 a;
    asm("{ .reg .u64 t; cvta.to.shared.u64 t, %1; cvt.u32.u64 %0, t; }" : "=r"(a) : "l"(p));
    return a;
}

#define CP_ASYNC16(dst, src) asm volatile("cp.async.cg.shared.global [%0], [%1], 16;" :: "r"(dst), "l"(src))
#define CP_COMMIT()          asm volatile("cp.async.commit_group;" ::: "memory")
#define CP_WAIT(n)           asm volatile("cp.async.wait_group %0;" :: "n"(n) : "memory")

#define LDSM4(r0, r1, r2, r3, addr) \
    asm volatile("ldmatrix.sync.aligned.m8n8.x4.shared.b16 {%0,%1,%2,%3}, [%4];" \
                 : "=r"(r0), "=r"(r1), "=r"(r2), "=r"(r3) : "r"(addr))

#define MMA16816(d, a0, a1, a2, a3, b0, b1) \
    asm volatile("mma.sync.aligned.m16n8k16.row.col.f32.f16.f16.f32 " \
                 "{%0,%1,%2,%3}, {%4,%5,%6,%7}, {%8,%9}, {%0,%1,%2,%3};" \
                 : "+f"((d)[0]), "+f"((d)[1]), "+f"((d)[2]), "+f"((d)[3]) \
                 : "r"(a0), "r"(a1), "r"(a2), "r"(a3), "r"(b0), "r"(b1))

__device__ __forceinline__ float softplus100(float v) {
    float y = 100.f * v;
    if (y > 20.f) return v;
    return log1pf(__expf(y)) * 0.01f;
}

// ---------------- weight-norm fold + fp16 round ---------------------------------
__global__ void prep_weights_tc(const float* __restrict__ v, const float* __restrict__ g,
                                int Kdim, int KPAD,
                                __half* __restrict__ W,
                                float* __restrict__ lastrow)
{
    int j = blockIdx.x;
    const float* vr = v + (size_t)j * Kdim;
    __shared__ float red[256];
    float s = 0.f;
    for (int k = threadIdx.x; k < Kdim; k += 256) { float t = vr[k]; s += t * t; }
    red[threadIdx.x] = s;
    __syncthreads();
    for (int st = 128; st > 0; st >>= 1) {
        if (threadIdx.x < st) red[threadIdx.x] += red[threadIdx.x + st];
        __syncthreads();
    }
    float scale = g[j] * rsqrtf(red[0]);
    if (lastrow != nullptr && j == 256) {
        for (int k = threadIdx.x; k < Kdim; k += 256) lastrow[k] = vr[k] * scale;
        return;
    }
    for (int k = threadIdx.x; k < Kdim; k += 256)
        W[(size_t)j * KPAD + k] = __float2half(vr[k] * scale);
}

// ---------------- encode: pos-embed + multires hash grid (fp16 out) -------------
__global__ void encode_kernel(const float* __restrict__ x,
                              const float* __restrict__ tab,
                              __half* __restrict__ F,
                              LevelParams lp)
{
    int i = blockIdx.x * blockDim.x + threadIdx.x;
    if (i >= NPTS) return;
    float px = x[3 * i + 0], py = x[3 * i + 1], pz = x[3 * i + 2];

    float vals[72];
    vals[0] = px; vals[1] = py; vals[2] = pz;
#pragma unroll
    for (int j = 0; j < 6; j++) {
        float f = (float)(1 << j);
        float s0, c0, s1, c1, s2, c2;
        __sincosf(f * px, &s0, &c0);
        __sincosf(f * py, &s1, &c1);
        __sincosf(f * pz, &s2, &c2);
        vals[3 + 6 * j + 0] = s0; vals[3 + 6 * j + 1] = s1; vals[3 + 6 * j + 2] = s2;
        vals[3 + 6 * j + 3] = c0; vals[3 + 6 * j + 4] = c1; vals[3 + 6 * j + 5] = c2;
    }

    float xc = fminf(fmaxf(px, 0.f), 1.f);
    float yc = fminf(fmaxf(py, 0.f), 1.f);
    float zc = fminf(fmaxf(pz, 0.f), 1.f);

#pragma unroll
    for (int l = 0; l < 16; l++) {
        int   R  = lp.R[l];
        float Rf = (float)R;
        float fx = xc * Rf, fy = yc * Rf, fz = zc * Rf;
        float f0x = floorf(fx), f0y = floorf(fy), f0z = floorf(fz);
        float w1x = fx - f0x, w1y = fy - f0y, w1z = fz - f0z;
        float wx[2] = {1.f - w1x, w1x};
        float wy[2] = {1.f - w1y, w1y};
        float wz[2] = {1.f - w1z, w1z};
        unsigned ux = (unsigned)f0x, uy = (unsigned)f0y, uz = (unsigned)f0z;
        unsigned Ru = (unsigned)R, R1 = Ru + 1u;
        int dns = lp.dense[l];
        const float2* tabL = (const float2*)tab + (size_t)l * TSZ;
        float ax = 0.f, ay = 0.f;
#pragma unroll
        for (int c = 0; c < 8; c++) {
            unsigned ox = c & 1, oy = (c >> 1) & 1, oz = (c >> 2) & 1;
            unsigned ix = min(ux + ox, Ru);
            unsigned iy = min(uy + oy, Ru);
            unsigned iz = min(uz + oz, Ru);
            unsigned flat;
            if (dns) flat = ix + R1 * (iy + R1 * iz);
            else     flat = (ix ^ (iy * P1) ^ (iz * P2)) & (TSZ - 1u);
            float wc = wx[ox] * wy[oy] * wz[oz];
            float2 tv = __ldg(&tabL[flat]);
            ax = fmaf(wc, tv.x, ax);
            ay = fmaf(wc, tv.y, ay);
        }
        vals[39 + 2 * l] = ax;
        vals[40 + 2 * l] = ay;
    }

    // vectorized fp16 store: 9 x uint4 (cols 0..71)
    __half* Fh = F + (size_t)i * KP0;
#pragma unroll
    for (int c0 = 0; c0 < 72; c0 += 8) {
        uint32 w[4];
#pragma unroll
        for (int q = 0; q < 4; q++) {
            __half2 hv = __floats2half2_rn(vals[c0 + 2 * q], vals[c0 + 2 * q + 1]);
            w[q] = *(uint32*)&hv;
        }
        *(uint4*)(Fh + c0) = make_uint4(w[0], w[1], w[2], w[3]);
    }
}

// ---------------- fp16 GEMM via mma.sync (HMMA), fp32 accumulate ----------------
// CTA tile 128(M) x 256(N full). 512 threads, 16 warps of 32x64
// (warpM = wid&3 -> 4x32 = 128 rows; warpN = wid>>2 -> 4x64 = 256 cols).
// B (weights) loaded into smem ONCE per CTA (135 KB resident);
// A double-buffered KC=64 chunks. Cuts LDGSTS op count ~1.7x vs R14
// (measured bottleneck = cp.async issue rate).
#define KC   64
#define ARS  144                       // A smem row stride (9 x 16B bank perm)
#define BRS  528                       // B smem row stride (33 x 16B, odd -> perm)
#define ATA  (128 * ARS)               // A tile array bytes  (18432)
#define BTOT (256 * BRS)               // B resident bytes    (135168)
#define SMEM_SZ (BTOT + 2 * ATA)       // 172032 -> 1 CTA/SM

template<int KPAD, bool ACT, bool LAST>
__global__ __launch_bounds__(512, 1)
void gemm_mma(const __half* __restrict__ A, const __half* __restrict__ B,
              const float* __restrict__ bias,
              const float* __restrict__ wlast,
              __half* __restrict__ O, float* __restrict__ Of)
{
    constexpr int NC = KPAD / KC;
    constexpr int BSLOTS = KPAD / 8;           // 16B slots per B row
    extern __shared__ char smem[];
    uint32 sb = smem_u32(smem);                // [B resident][A stage0][A stage1]

    const int tid  = threadIdx.x;
    const int lane = tid & 31;
    const int wid  = tid >> 5;
    const int warpM = wid & 3;                 // 0..3 -> 32-row slice
    const int warpN = wid >> 2;                // 0..3 -> 64-col slice
    const int mBase = blockIdx.x * 128;

    // A loader mapping: chunk = 128 rows x 8 slots = 1024 -> 2/thread
    const int aRow = tid >> 3, aSlot = tid & 7;   // aRow 0..63 (+64)

    const char* pA = (const char*)(A + (size_t)mBase * KPAD);
    const char* pB = (const char*)B;

    // ---- one-time B load: 256 rows x BSLOTS 16B chunks ----
    {
        constexpr int TOT = 256 * BSLOTS;
#pragma unroll
        for (int t = 0; t < TOT / 512; t++) {
            int j = tid + t * 512;
            int row = j / BSLOTS, slot = j % BSLOTS;
            CP_ASYNC16(sb + row * BRS + slot * 16,
                       pB + (size_t)row * (KPAD * 2) + slot * 16);
        }
        CP_COMMIT();
    }

    auto issue_chunk = [&](int c) {
        uint32 stage = sb + BTOT + (c & 1) * ATA;
#pragma unroll
        for (int t = 0; t < 2; t++) {
            int row = aRow + t * 64;
            size_t ga = (size_t)row * (KPAD * 2) + c * (KC * 2) + aSlot * 16;
            CP_ASYNC16(stage + row * ARS + aSlot * 16, pA + ga);
        }
        CP_COMMIT();
    };

    float acc[2][8][4];
#pragma unroll
    for (int mt = 0; mt < 2; mt++)
#pragma unroll
        for (int nt = 0; nt < 8; nt++)
#pragma unroll
            for (int q = 0; q < 4; q++) acc[mt][nt][q] = 0.f;

    float accL[2] = {0.f, 0.f};                // fused 257th-col dots (LAST)

    const uint32 aOff = (uint32)(warpM * 32 + (lane & 15)) * ARS + (lane >> 4) * 16;
    const uint32 bOff = (uint32)(warpN * 64 + (lane & 7) + ((lane >> 4) << 3)) * BRS
                        + ((lane >> 3) & 1) * 16;

    issue_chunk(0);

    for (int c = 0; c < NC; c++) {
        // wait for all outstanding groups (B + chunk c at c==0; chunk c later);
        // barrier publishes data and certifies compute of c-1 done.
        CP_WAIT(0);
        __syncthreads();
        if (c + 1 < NC) issue_chunk(c + 1);    // overlaps compute of chunk c

        uint32 stage = sb + BTOT + (c & 1) * ATA;
        uint32 sA = stage + aOff;
        uint32 sBc = sb + bOff + c * (KC * 2);

        if (LAST) {
            const float* wsp = wlast + c * KC + aSlot * 8;
#pragma unroll
            for (int t = 0; t < 2; t++) {
                uint32 aAddr = stage + (aRow + t * 64) * ARS + aSlot * 16;
                uint32 av0, av1, av2, av3;
                asm volatile("ld.shared.v4.u32 {%0,%1,%2,%3}, [%4];"
                             : "=r"(av0), "=r"(av1), "=r"(av2), "=r"(av3) : "r"(aAddr));
                uint32 avw[4] = {av0, av1, av2, av3};
                float accv = 0.f;
#pragma unroll
                for (int j = 0; j < 4; j++) {
                    __half2 h = *(__half2*)&avw[j];
                    float2 f = __half22float2(h);
                    accv = fmaf(f.x, __ldg(wsp + 2 * j),     accv);
                    accv = fmaf(f.y, __ldg(wsp + 2 * j + 1), accv);
                }
                accL[t] += accv;
            }
        }

#pragma unroll
        for (int ks = 0; ks < 4; ks++) {
            uint32 kb = ks * 32;               // 16 k-elems = 32 bytes
            uint32 a[2][4];
            LDSM4(a[0][0], a[0][1], a[0][2], a[0][3], sA + kb);
            LDSM4(a[1][0], a[1][1], a[1][2], a[1][3], sA + 16 * ARS + kb);
#pragma unroll
            for (int np = 0; np < 4; np++) {
                uint32 b[4];
                LDSM4(b[0], b[1], b[2], b[3], sBc + np * 16 * BRS + kb);
#pragma unroll
                for (int mt = 0; mt < 2; mt++) {
                    MMA16816(acc[mt][2 * np + 0], a[mt][0], a[mt][1], a[mt][2], a[mt][3], b[0], b[1]);
                    MMA16816(acc[mt][2 * np + 1], a[mt][0], a[mt][1], a[mt][2], a[mt][3], b[2], b[3]);
                }
            }
        }
    }

    // ---------------- fused last column: reduce across the 8 slot-threads -------
    if (LAST) {
#pragma unroll
        for (int t = 0; t < 2; t++) {
            accL[t] += __shfl_xor_sync(0xffffffffu, accL[t], 1);
            accL[t] += __shfl_xor_sync(0xffffffffu, accL[t], 2);
            accL[t] += __shfl_xor_sync(0xffffffffu, accL[t], 4);
        }
        if (aSlot == 0) {
            float blast = __ldg(bias + 256);
            Of[(size_t)(mBase + aRow)      * 257 + 256] = accL[0] + blast;
            Of[(size_t)(mBase + aRow + 64) * 257 + 256] = accL[1] + blast;
        }
    }

    // ---------------- epilogue: bias + act + store ------------------------------
#pragma unroll
    for (int mt = 0; mt < 2; mt++) {
        int m0 = mBase + warpM * 32 + mt * 16 + (lane >> 2);
#pragma unroll
        for (int nt = 0; nt < 8; nt++) {
            int n0 = warpN * 64 + nt * 8 + (lane & 3) * 2;
            float bj0 = __ldg(bias + n0), bj1 = __ldg(bias + n0 + 1);
#pragma unroll
            for (int half = 0; half < 2; half++) {
                int m = m0 + half * 8;
                float v0 = acc[mt][nt][2 * half + 0] + bj0;
                float v1 = acc[mt][nt][2 * half + 1] + bj1;
                if (ACT) { v0 = softplus100(v0); v1 = softplus100(v1); }
                if (LAST) {
                    float* orow = Of + (size_t)m * 257 + n0;
                    orow[0] = v0; orow[1] = v1;
                } else {
                    __half2 hv = __floats2half2_rn(v0, v1);
                    *(__half2*)(O + (size_t)m * 256 + n0) = hv;
                }
            }
        }
    }
}

// ---------------- launch --------------------------------------------------------
extern "C" void kernel_launch(void* const* d_in, const int* in_sizes, int n_in,
                              void* d_out, int out_size)
{
    const float* x      = (const float*)d_in[0];
    const float* tables = (const float*)d_in[1];
    const float* v0 = (const float*)d_in[2];
    const float* g0 = (const float*)d_in[3];
    const float* b0 = (const float*)d_in[4];
    const float* v1 = (const float*)d_in[5];
    const float* g1 = (const float*)d_in[6];
    const float* b1 = (const float*)d_in[7];
    const float* v2 = (const float*)d_in[8];
    const float* g2 = (const float*)d_in[9];
    const float* b2 = (const float*)d_in[10];
    float* out = (float*)d_out;

    __half *F, *H0, *H1, *W0, *W1, *W2;
    float* w2last;
    cudaGetSymbolAddress((void**)&F,  g_F);
    cudaGetSymbolAddress((void**)&H0, g_H0);
    cudaGetSymbolAddress((void**)&H1, g_H1);
    cudaGetSymbolAddress((void**)&W0, g_W0);
    cudaGetSymbolAddress((void**)&W1, g_W1);
    cudaGetSymbolAddress((void**)&W2, g_W2);
    cudaGetSymbolAddress((void**)&w2last, g_w2last);

    LevelParams lp;
    double SCALE = pow(2.0, log2(2048.0 / 16.0) / 15.0);
    for (int l = 0; l < 16; l++) {
        int R = (int)ceil(16.0 * pow(SCALE, (double)l));
        lp.R[l] = R;
        long long cc = (long long)R + 1;
        lp.dense[l] = (cc * cc * cc <= (long long)TSZ) ? 1 : 0;
    }

    cudaFuncSetAttribute(gemm_mma<KP0, true,  false>, cudaFuncAttributeMaxDynamicSharedMemorySize, SMEM_SZ);
    cudaFuncSetAttribute(gemm_mma<256, true,  false>, cudaFuncAttributeMaxDynamicSharedMemorySize, SMEM_SZ);
    cudaFuncSetAttribute(gemm_mma<256, false, true >, cudaFuncAttributeMaxDynamicSharedMemorySize, SMEM_SZ);

    prep_weights_tc<<<256, 256>>>(v0, g0, 71,  KP0, W0, nullptr);
    prep_weights_tc<<<256, 256>>>(v1, g1, 256, 256, W1, nullptr);
    prep_weights_tc<<<257, 256>>>(v2, g2, 256, 256, W2, w2last);

    encode_kernel<<<NPTS / 256, 256>>>(x, tables, F, lp);

    gemm_mma<KP0, true,  false><<<NPTS / 128, 512, SMEM_SZ>>>(F,  W0, b0, nullptr, H0, nullptr);
    gemm_mma<256, true,  false><<<NPTS / 128, 512, SMEM_SZ>>>(H0, W1, b1, nullptr, H1, nullptr);
    gemm_mma<256, false, true ><<<NPTS / 128, 512, SMEM_SZ>>>(H1, W2, b2, w2last, nullptr, out);
}

// round 17
// speedup vs baseline: 1.1096x; 1.1096x over previous
#include <cuda_runtime.h>
#include <cuda_fp16.h>
#include <math.h>
#include <stdint.h>

typedef unsigned int uint32;

#define NPTS 524288
#define TSZ  (1u << 19)
#define P1   2654435761u
#define P2   805459861u

#define KP0  128                       // layer-0 K padding (71 real cols)

// ---------------- scratch (device globals; allocation-free rule) ----------------
// Padding regions (cols 71..127 of F, rows k>=71 of W0) are BSS-zero (fp16 +0.0)
// and never written by any kernel, so they stay zero across graph replays.
__device__ __half g_F [(size_t)NPTS * KP0];
__device__ __half g_H0[(size_t)NPTS * 256];
__device__ __half g_H1[(size_t)NPTS * 256];
__device__ __half g_W0[256 * KP0];             // [N=256][Kpad] K-major
__device__ __half g_W1[256 * 256];
__device__ __half g_W2[256 * 256];             // rows 0..255 of v2
__device__ float  g_w2last[256];               // row 256 of v2 (folded)

struct LevelParams { int R[16]; int dense[16]; };

// ---------------- PTX helpers ---------------------------------------------------
__device__ __forceinline__ uint32 smem_u32(const void* p) {
    uint32 a;
    asm("{ .reg .u64 t; cvta.to.shared.u64 t, %1; cvt.u32.u64 %0, t; }" : "=r"(a) : "l"(p));
    return a;
}

#define CP_ASYNC16(dst, src) asm volatile("cp.async.cg.shared.global [%0], [%1], 16;" :: "r"(dst), "l"(src))
#define CP_COMMIT()          asm volatile("cp.async.commit_group;" ::: "memory")
#define CP_WAIT(n)           asm volatile("cp.async.wait_group %0;" :: "n"(n) : "memory")

#define LDSM4(r0, r1, r2, r3, addr) \
    asm volatile("ldmatrix.sync.aligned.m8n8.x4.shared.b16 {%0,%1,%2,%3}, [%4];" \
                 : "=r"(r0), "=r"(r1), "=r"(r2), "=r"(r3) : "r"(addr))

#define MMA16816(d, a0, a1, a2, a3, b0, b1) \
    asm volatile("mma.sync.aligned.m16n8k16.row.col.f32.f16.f16.f32 " \
                 "{%0,%1,%2,%3}, {%4,%5,%6,%7}, {%8,%9}, {%0,%1,%2,%3};" \
                 : "+f"((d)[0]), "+f"((d)[1]), "+f"((d)[2]), "+f"((d)[3]) \
                 : "r"(a0), "r"(a1), "r"(a2), "r"(a3), "r"(b0), "r"(b1))

__device__ __forceinline__ float softplus100(float v) {
    float y = 100.f * v;
    if (y > 20.f) return v;
    return log1pf(__expf(y)) * 0.01f;
}

// ---------------- weight-norm fold + fp16 round ---------------------------------
__global__ void prep_weights_tc(const float* __restrict__ v, const float* __restrict__ g,
                                int Kdim, int KPAD,
                                __half* __restrict__ W,
                                float* __restrict__ lastrow)
{
    int j = blockIdx.x;
    const float* vr = v + (size_t)j * Kdim;
    __shared__ float red[256];
    float s = 0.f;
    for (int k = threadIdx.x; k < Kdim; k += 256) { float t = vr[k]; s += t * t; }
    red[threadIdx.x] = s;
    __syncthreads();
    for (int st = 128; st > 0; st >>= 1) {
        if (threadIdx.x < st) red[threadIdx.x] += red[threadIdx.x + st];
        __syncthreads();
    }
    float scale = g[j] * rsqrtf(red[0]);
    if (lastrow != nullptr && j == 256) {
        for (int k = threadIdx.x; k < Kdim; k += 256) lastrow[k] = vr[k] * scale;
        return;
    }
    for (int k = threadIdx.x; k < Kdim; k += 256)
        W[(size_t)j * KPAD + k] = __float2half(vr[k] * scale);
}

// ---------------- encode: pos-embed + multires hash grid (fp16 out) -------------
__global__ void encode_kernel(const float* __restrict__ x,
                              const float* __restrict__ tab,
                              __half* __restrict__ F,
                              LevelParams lp)
{
    int i = blockIdx.x * blockDim.x + threadIdx.x;
    if (i >= NPTS) return;
    float px = x[3 * i + 0], py = x[3 * i + 1], pz = x[3 * i + 2];

    float vals[72];
    vals[0] = px; vals[1] = py; vals[2] = pz;
#pragma unroll
    for (int j = 0; j < 6; j++) {
        float f = (float)(1 << j);
        float s0, c0, s1, c1, s2, c2;
        __sincosf(f * px, &s0, &c0);
        __sincosf(f * py, &s1, &c1);
        __sincosf(f * pz, &s2, &c2);
        vals[3 + 6 * j + 0] = s0; vals[3 + 6 * j + 1] = s1; vals[3 + 6 * j + 2] = s2;
        vals[3 + 6 * j + 3] = c0; vals[3 + 6 * j + 4] = c1; vals[3 + 6 * j + 5] = c2;
    }

    float xc = fminf(fmaxf(px, 0.f), 1.f);
    float yc = fminf(fmaxf(py, 0.f), 1.f);
    float zc = fminf(fmaxf(pz, 0.f), 1.f);

#pragma unroll
    for (int l = 0; l < 16; l++) {
        int   R  = lp.R[l];
        float Rf = (float)R;
        float fx = xc * Rf, fy = yc * Rf, fz = zc * Rf;
        float f0x = floorf(fx), f0y = floorf(fy), f0z = floorf(fz);
        float w1x = fx - f0x, w1y = fy - f0y, w1z = fz - f0z;
        float wx[2] = {1.f - w1x, w1x};
        float wy[2] = {1.f - w1y, w1y};
        float wz[2] = {1.f - w1z, w1z};
        unsigned ux = (unsigned)f0x, uy = (unsigned)f0y, uz = (unsigned)f0z;
        unsigned Ru = (unsigned)R, R1 = Ru + 1u;
        int dns = lp.dense[l];
        const float2* tabL = (const float2*)tab + (size_t)l * TSZ;
        float ax = 0.f, ay = 0.f;
#pragma unroll
        for (int c = 0; c < 8; c++) {
            unsigned ox = c & 1, oy = (c >> 1) & 1, oz = (c >> 2) & 1;
            unsigned ix = min(ux + ox, Ru);
            unsigned iy = min(uy + oy, Ru);
            unsigned iz = min(uz + oz, Ru);
            unsigned flat;
            if (dns) flat = ix + R1 * (iy + R1 * iz);
            else     flat = (ix ^ (iy * P1) ^ (iz * P2)) & (TSZ - 1u);
            float wc = wx[ox] * wy[oy] * wz[oz];
            float2 tv = __ldg(&tabL[flat]);
            ax = fmaf(wc, tv.x, ax);
            ay = fmaf(wc, tv.y, ay);
        }
        vals[39 + 2 * l] = ax;
        vals[40 + 2 * l] = ay;
    }

    // vectorized fp16 store: 9 x uint4 (cols 0..71)
    __half* Fh = F + (size_t)i * KP0;
#pragma unroll
    for (int c0 = 0; c0 < 72; c0 += 8) {
        uint32 w[4];
#pragma unroll
        for (int q = 0; q < 4; q++) {
            __half2 hv = __floats2half2_rn(vals[c0 + 2 * q], vals[c0 + 2 * q + 1]);
            w[q] = *(uint32*)&hv;
        }
        *(uint4*)(Fh + c0) = make_uint4(w[0], w[1], w[2], w[3]);
    }
}

// ---------------- fp16 GEMM via mma.sync (HMMA), fp32 accumulate ----------------
// PERSISTENT B-resident kernel, 2 CTAs/SM preserved:
//   grid (148, 2): blockIdx.y selects an N-half (128 cols); each CTA loads its
//   B half into smem ONCE (67.6 KB) and sweeps M-tiles of 64 rows persistently.
//   256 threads, 8 warps of 32x32 (warpM 0..1, warpN 0..3). A double-buffered
//   KC=64 chunks; one __syncthreads per chunk; cross-tile chunk prefetch.
#define KC   64
#define ARS  144                       // A smem row stride (9 x 16B bank perm)
#define BRS  528                       // B smem row stride (33 x 16B, odd -> perm)
#define ATA  (64 * ARS)                // A tile array bytes  (9216)
#define BTOT (128 * BRS)               // B half resident     (67584)
#define SMEM_SZ (BTOT + 2 * ATA)       // 86016 -> 2 CTAs/SM
#define GRIDX 148

template<int KPAD, bool ACT, bool LAST>
__global__ __launch_bounds__(256, 2)
void gemm_mma(const __half* __restrict__ A, const __half* __restrict__ B,
              const float* __restrict__ bias,
              const float* __restrict__ wlast,
              __half* __restrict__ O, float* __restrict__ Of)
{
    constexpr int NC = KPAD / KC;
    constexpr int NT = NPTS / 64;              // 8192 M-tiles
    constexpr int BSLOTS = KPAD / 8;           // 16B slots per B row
    extern __shared__ char smem[];
    uint32 sb = smem_u32(smem);                // [B half][A stage0][A stage1]

    const int tid  = threadIdx.x;
    const int lane = tid & 31;
    const int wid  = tid >> 5;
    const int warpM = wid & 1;                 // 0..1 -> 32-row slice
    const int warpN = wid >> 1;                // 0..3 -> 32-col slice
    const int nHalf = blockIdx.y;
    const int nBase = nHalf * 128;
    const bool doLast = LAST && (nHalf == 0);

    // A loader mapping: chunk = 64 rows x 8 slots = 512 -> 2/thread
    const int aRow = tid >> 3, aSlot = tid & 7;   // aRow 0..31 (+32)

    const char* pB = (const char*)B;

    // ---- one-time B-half load: 128 rows x BSLOTS 16B chunks ----
    {
        constexpr int TOT = 128 * BSLOTS;
#pragma unroll
        for (int t = 0; t < TOT / 256; t++) {
            int j = tid + t * 256;
            int row = j / BSLOTS, slot = j % BSLOTS;
            CP_ASYNC16(sb + row * BRS + slot * 16,
                       pB + (size_t)(nBase + row) * (KPAD * 2) + slot * 16);
        }
        CP_COMMIT();
    }

    auto issueA = [&](int tile, int c, int buf) {
        uint32 stage = sb + BTOT + buf * ATA;
        const char* pA = (const char*)(A + (size_t)tile * 64 * KPAD);
#pragma unroll
        for (int t = 0; t < 2; t++) {
            int row = aRow + t * 32;
            CP_ASYNC16(stage + row * ARS + aSlot * 16,
                       pA + (size_t)row * (KPAD * 2) + c * (KC * 2) + aSlot * 16);
        }
        CP_COMMIT();
    };

    const uint32 aOff = (uint32)(warpM * 32 + (lane & 15)) * ARS + (lane >> 4) * 16;
    const uint32 bOff = (uint32)(warpN * 32 + (lane & 7) + ((lane >> 4) << 3)) * BRS
                        + ((lane >> 3) & 1) * 16;

    int buf = 0;
    issueA(blockIdx.x, 0, 0);

    for (int tile = blockIdx.x; tile < NT; tile += GRIDX) {
        const int mBase = tile * 64;
        float acc[2][4][4];
#pragma unroll
        for (int mt = 0; mt < 2; mt++)
#pragma unroll
            for (int nt = 0; nt < 4; nt++)
#pragma unroll
                for (int q = 0; q < 4; q++) acc[mt][nt][q] = 0.f;
        float accL[2] = {0.f, 0.f};

        for (int c = 0; c < NC; c++) {
            // drain everything in flight (chunk (tile,c), plus B on the very
            // first pass); barrier publishes data AND certifies the previous
            // chunk's compute finished, so buf^1 is free to refill.
            CP_WAIT(0);
            __syncthreads();
            if (c + 1 < NC)              issueA(tile, c + 1, buf ^ 1);
            else if (tile + GRIDX < NT)  issueA(tile + GRIDX, 0, buf ^ 1);

            uint32 stage = sb + BTOT + buf * ATA;
            uint32 sA  = stage + aOff;
            uint32 sBc = sb + bOff + c * (KC * 2);

            if (doLast) {
                const float* wsp = wlast + c * KC + aSlot * 8;
#pragma unroll
                for (int t = 0; t < 2; t++) {
                    uint32 aAddr = stage + (aRow + t * 32) * ARS + aSlot * 16;
                    uint32 av0, av1, av2, av3;
                    asm volatile("ld.shared.v4.u32 {%0,%1,%2,%3}, [%4];"
                                 : "=r"(av0), "=r"(av1), "=r"(av2), "=r"(av3) : "r"(aAddr));
                    uint32 avw[4] = {av0, av1, av2, av3};
                    float accv = 0.f;
#pragma unroll
                    for (int j = 0; j < 4; j++) {
                        __half2 h = *(__half2*)&avw[j];
                        float2 f = __half22float2(h);
                        accv = fmaf(f.x, __ldg(wsp + 2 * j),     accv);
                        accv = fmaf(f.y, __ldg(wsp + 2 * j + 1), accv);
                    }
                    accL[t] += accv;
                }
            }

#pragma unroll
            for (int ks = 0; ks < 4; ks++) {
                uint32 kb = ks * 32;           // 16 k-elems = 32 bytes
                uint32 a[2][4];
                LDSM4(a[0][0], a[0][1], a[0][2], a[0][3], sA + kb);
                LDSM4(a[1][0], a[1][1], a[1][2], a[1][3], sA + 16 * ARS + kb);
#pragma unroll
                for (int np = 0; np < 2; np++) {
                    uint32 b[4];
                    LDSM4(b[0], b[1], b[2], b[3], sBc + np * 16 * BRS + kb);
#pragma unroll
                    for (int mt = 0; mt < 2; mt++) {
                        MMA16816(acc[mt][2 * np + 0], a[mt][0], a[mt][1], a[mt][2], a[mt][3], b[0], b[1]);
                        MMA16816(acc[mt][2 * np + 1], a[mt][0], a[mt][1], a[mt][2], a[mt][3], b[2], b[3]);
                    }
                }
            }
            buf ^= 1;
        }

        // ---- fused last column (nHalf 0 only): reduce across 8 slot lanes ----
        if (doLast) {
#pragma unroll
            for (int t = 0; t < 2; t++) {
                accL[t] += __shfl_xor_sync(0xffffffffu, accL[t], 1);
                accL[t] += __shfl_xor_sync(0xffffffffu, accL[t], 2);
                accL[t] += __shfl_xor_sync(0xffffffffu, accL[t], 4);
            }
            if (aSlot == 0) {
                float blast = __ldg(bias + 256);
                Of[(size_t)(mBase + aRow)      * 257 + 256] = accL[0] + blast;
                Of[(size_t)(mBase + aRow + 32) * 257 + 256] = accL[1] + blast;
            }
        }

        // ---- epilogue: bias + act + store (gmem only; overlaps next prefetch) --
#pragma unroll
        for (int mt = 0; mt < 2; mt++) {
            int m0 = mBase + warpM * 32 + mt * 16 + (lane >> 2);
#pragma unroll
            for (int nt = 0; nt < 4; nt++) {
                int n0 = nBase + warpN * 32 + nt * 8 + (lane & 3) * 2;
                float bj0 = __ldg(bias + n0), bj1 = __ldg(bias + n0 + 1);
#pragma unroll
                for (int half = 0; half < 2; half++) {
                    int m = m0 + half * 8;
                    float v0 = acc[mt][nt][2 * half + 0] + bj0;
                    float v1 = acc[mt][nt][2 * half + 1] + bj1;
                    if (ACT) { v0 = softplus100(v0); v1 = softplus100(v1); }
                    if (LAST) {
                        float* orow = Of + (size_t)m * 257 + n0;
                        orow[0] = v0; orow[1] = v1;
                    } else {
                        __half2 hv = __floats2half2_rn(v0, v1);
                        *(__half2*)(O + (size_t)m * 256 + n0) = hv;
                    }
                }
            }
        }
    }
}

// ---------------- launch --------------------------------------------------------
extern "C" void kernel_launch(void* const* d_in, const int* in_sizes, int n_in,
                              void* d_out, int out_size)
{
    const float* x      = (const float*)d_in[0];
    const float* tables = (const float*)d_in[1];
    const float* v0 = (const float*)d_in[2];
    const float* g0 = (const float*)d_in[3];
    const float* b0 = (const float*)d_in[4];
    const float* v1 = (const float*)d_in[5];
    const float* g1 = (const float*)d_in[6];
    const float* b1 = (const float*)d_in[7];
    const float* v2 = (const float*)d_in[8];
    const float* g2 = (const float*)d_in[9];
    const float* b2 = (const float*)d_in[10];
    float* out = (float*)d_out;

    __half *F, *H0, *H1, *W0, *W1, *W2;
    float* w2last;
    cudaGetSymbolAddress((void**)&F,  g_F);
    cudaGetSymbolAddress((void**)&H0, g_H0);
    cudaGetSymbolAddress((void**)&H1, g_H1);
    cudaGetSymbolAddress((void**)&W0, g_W0);
    cudaGetSymbolAddress((void**)&W1, g_W1);
    cudaGetSymbolAddress((void**)&W2, g_W2);
    cudaGetSymbolAddress((void**)&w2last, g_w2last);

    LevelParams lp;
    double SCALE = pow(2.0, log2(2048.0 / 16.0) / 15.0);
    for (int l = 0; l < 16; l++) {
        int R = (int)ceil(16.0 * pow(SCALE, (double)l));
        lp.R[l] = R;
        long long cc = (long long)R + 1;
        lp.dense[l] = (cc * cc * cc <= (long long)TSZ) ? 1 : 0;
    }

    cudaFuncSetAttribute(gemm_mma<KP0, true,  false>, cudaFuncAttributeMaxDynamicSharedMemorySize, SMEM_SZ);
    cudaFuncSetAttribute(gemm_mma<256, true,  false>, cudaFuncAttributeMaxDynamicSharedMemorySize, SMEM_SZ);
    cudaFuncSetAttribute(gemm_mma<256, false, true >, cudaFuncAttributeMaxDynamicSharedMemorySize, SMEM_SZ);

    prep_weights_tc<<<256, 256>>>(v0, g0, 71,  KP0, W0, nullptr);
    prep_weights_tc<<<256, 256>>>(v1, g1, 256, 256, W1, nullptr);
    prep_weights_tc<<<257, 256>>>(v2, g2, 256, 256, W2, w2last);

    encode_kernel<<<NPTS / 256, 256>>>(x, tables, F, lp);

    dim3 grid(GRIDX, 2);
    gemm_mma<KP0, true,  false><<<grid, 256, SMEM_SZ>>>(F,  W0, b0, nullptr, H0, nullptr);
    gemm_mma<256, true,  false><<<grid, 256, SMEM_SZ>>>(H0, W1, b1, nullptr, H1, nullptr);
    gemm_mma<256, false, true ><<<grid, 256, SMEM_SZ>>>(H1, W2, b2, w2last, nullptr, out);
}